// round 1
// baseline (speedup 1.0000x reference)
#include <cuda_runtime.h>
#include <cuda_bf16.h>
#include <cstdint>
#include <cstddef>

// Problem shape (fixed): B=2, S=2048 -> T=4096 tokens, D=1024, W=4096, SLOT=8,
// C=11 (8 slots + consts {-1,0,1}), TREE_DEPTH=3 -> 8 leaves.
#define T_TOK   4096
#define DIM     1024
#define NW      4096
#define NSLOT   8
#define NLEAF   8

// Scratch (device globals; no allocation allowed in kernel_launch)
__device__ float g_slots[T_TOK * NSLOT];             // tanh(hidden@slot_w+b)
__device__ float g_sel[NW * NLEAF * 9];              // softmax sel[0..7] + folded bias (sel10-sel8)
__device__ float g_roots[(size_t)T_TOK * NW];        // 64 MB intermediate

// ---------------------------------------------------------------------------
// accurate-enough tanh via __expf (rel err ~1e-6)
__device__ __forceinline__ float tanh_fast(float x) {
    float ax = fabsf(x);
    float e  = __expf(-2.0f * ax);          // (0,1]
    float r  = __fdividef(1.0f - e, 1.0f + e);
    return copysignf(r, x);
}

// ---------------------------------------------------------------------------
// Kernel A: slots[t][s] = tanh( sum_d hidden[t][d]*slot_w[d][s] + slot_b[s] )
// one block (128 thr) per token
__global__ __launch_bounds__(128) void slots_kernel(
    const float* __restrict__ hidden,
    const float* __restrict__ slot_w,
    const float* __restrict__ slot_b)
{
    int t = blockIdx.x;
    const float* h = hidden + (size_t)t * DIM;
    float acc[NSLOT];
#pragma unroll
    for (int s = 0; s < NSLOT; ++s) acc[s] = 0.0f;

#pragma unroll
    for (int it = 0; it < 2; ++it) {
        int d = threadIdx.x * 4 + it * 512;
        float4 hv = *(const float4*)(h + d);
#pragma unroll
        for (int j = 0; j < 4; ++j) {
            float hx = (j == 0) ? hv.x : (j == 1) ? hv.y : (j == 2) ? hv.z : hv.w;
            const float* wr = slot_w + (size_t)(d + j) * NSLOT;
            float4 w0 = *(const float4*)(wr);
            float4 w1 = *(const float4*)(wr + 4);
            acc[0] = fmaf(hx, w0.x, acc[0]);
            acc[1] = fmaf(hx, w0.y, acc[1]);
            acc[2] = fmaf(hx, w0.z, acc[2]);
            acc[3] = fmaf(hx, w0.w, acc[3]);
            acc[4] = fmaf(hx, w1.x, acc[4]);
            acc[5] = fmaf(hx, w1.y, acc[5]);
            acc[6] = fmaf(hx, w1.z, acc[6]);
            acc[7] = fmaf(hx, w1.w, acc[7]);
        }
    }

    // warp butterfly reduce (every lane ends with warp sum)
#pragma unroll
    for (int s = 0; s < NSLOT; ++s) {
        float v = acc[s];
#pragma unroll
        for (int off = 16; off; off >>= 1)
            v += __shfl_xor_sync(0xffffffffu, v, off);
        acc[s] = v;
    }

    __shared__ float red[4][NSLOT];
    int lane = threadIdx.x & 31, warp = threadIdx.x >> 5;
    if (lane == 0) {
#pragma unroll
        for (int s = 0; s < NSLOT; ++s) red[warp][s] = acc[s];
    }
    __syncthreads();
    if (threadIdx.x < NSLOT) {
        int s = threadIdx.x;
        float v = red[0][s] + red[1][s] + red[2][s] + red[3][s] + slot_b[s];
        g_slots[(size_t)t * NSLOT + s] = tanhf(v);
    }
}

// ---------------------------------------------------------------------------
// Kernel B: per (w,l) softmax over 11 logits; store sel[0..7] and
// bias = sel[10] - sel[8]   (basis consts are -1, 0, 1)
__global__ __launch_bounds__(256) void softmax_kernel(const float* __restrict__ logits)
{
    int r = blockIdx.x * blockDim.x + threadIdx.x;   // (w*8 + l), 0..32767
    if (r >= NW * NLEAF) return;
    const float* row = logits + (size_t)r * 11;
    float x[11];
    float m = -1e30f;
#pragma unroll
    for (int c = 0; c < 11; ++c) { x[c] = row[c]; m = fmaxf(m, x[c]); }
    float sum = 0.0f;
#pragma unroll
    for (int c = 0; c < 11; ++c) { x[c] = __expf(x[c] - m); sum += x[c]; }
    float inv = 1.0f / sum;
    float* o = g_sel + (size_t)r * 9;
#pragma unroll
    for (int c = 0; c < 8; ++c) o[c] = x[c] * inv;
    o[8] = (x[10] - x[8]) * inv;
}

// ---------------------------------------------------------------------------
// Kernel C: fused leaf einsum + tree reduce.
// Block tile: 64 w x 16 tokens; thread = 1 w x 4 tokens.
#define WPB 64
#define TPB 16
__global__ __launch_bounds__(256) void roots_kernel(const float* __restrict__ node_params)
{
    __shared__ float s_sel[WPB * 73];     // per-w stride 73 (odd vs 32 banks)
    __shared__ float s_slot[TPB][NSLOT];

    int w0 = blockIdx.x * WPB;
    int t0 = blockIdx.y * TPB;

    // load selector tile (64 * 72 contiguous floats, repack to stride 73)
    const float* gs = g_sel + (size_t)w0 * 72;
    for (int i = threadIdx.x; i < WPB * 72; i += 256) {
        int w = i / 72, j = i - w * 72;
        s_sel[w * 73 + j] = gs[i];
    }
    // load slots for 16 tokens
    if (threadIdx.x < TPB * NSLOT) {
        int tt = threadIdx.x >> 3, c = threadIdx.x & 7;
        s_slot[tt][c] = g_slots[(size_t)(t0 + tt) * NSLOT + c];
    }
    __syncthreads();

    int wq = threadIdx.x & 63;
    int tg = threadIdx.x >> 6;    // token group 0..3 (4 tokens each)

    float lw = node_params[0], rw = node_params[1], pw = node_params[2];
    float dw = node_params[3], nb = node_params[4];

    float slot[4][NSLOT];
#pragma unroll
    for (int t = 0; t < 4; ++t)
#pragma unroll
        for (int c = 0; c < NSLOT; ++c)
            slot[t][c] = s_slot[tg * 4 + t][c];

    const float* sel = s_sel + wq * 73;
    float v[4][NLEAF];
#pragma unroll
    for (int l = 0; l < NLEAF; ++l) {
        float bias = sel[l * 9 + 8];
        float v0 = bias, v1 = bias, v2 = bias, v3 = bias;
#pragma unroll
        for (int c = 0; c < 8; ++c) {
            float sc = sel[l * 9 + c];
            v0 = fmaf(sc, slot[0][c], v0);
            v1 = fmaf(sc, slot[1][c], v1);
            v2 = fmaf(sc, slot[2][c], v2);
            v3 = fmaf(sc, slot[3][c], v3);
        }
        v[0][l] = v0; v[1][l] = v1; v[2][l] = v2; v[3][l] = v3;
    }

    // tree reduce: 8 -> 4 -> 2 -> 1
#pragma unroll
    for (int t = 0; t < 4; ++t) {
        float* x = v[t];
#pragma unroll
        for (int d = 0; d < 3; ++d) {
            int n = NLEAF >> (d + 1);
#pragma unroll
            for (int i = 0; i < 8; ++i) {
                if (i < n) {
                    float L = x[2 * i], R = x[2 * i + 1];
                    float z = fmaf(lw, L, nb);
                    z = fmaf(rw, R, z);
                    z = fmaf(pw, L * R, z);
                    z = fmaf(dw, L - R, z);
                    x[i] = tanh_fast(z);
                }
            }
        }
    }

#pragma unroll
    for (int t = 0; t < 4; ++t) {
        int tok = t0 + tg * 4 + t;
        g_roots[(size_t)tok * NW + w0 + wq] = v[t][0];
    }
}

// ---------------------------------------------------------------------------
// Kernel D: out[t][d] = sum_w roots[t][w] * out_w[w][d] + out_b[d]
// M=4096, N=1024, K=4096. 128x128 block tile, 8x8/thread, BK=8, double-buffered.
__global__ __launch_bounds__(256, 2) void gemm_kernel(
    const float* __restrict__ Bw,
    const float* __restrict__ bias,
    float* __restrict__ C)
{
    __shared__ float As[2][8][132];
    __shared__ float Bs[2][8][128];

    const float* A = g_roots;
    int bm = blockIdx.y << 7;
    int bn = blockIdx.x << 7;
    int tid = threadIdx.x;

    int arow = tid >> 1;            // 0..127
    int acol = (tid & 1) << 2;      // 0 / 4
    int brow = tid >> 5;            // 0..7
    int bcol = (tid & 31) << 2;     // 0..124

    const float* Ap = A + (size_t)(bm + arow) * NW + acol;
    const float* Bp = Bw + (size_t)brow * DIM + bn + bcol;

    float4 a4 = *(const float4*)Ap;
    float4 b4 = *(const float4*)Bp;
    As[0][acol + 0][arow] = a4.x;
    As[0][acol + 1][arow] = a4.y;
    As[0][acol + 2][arow] = a4.z;
    As[0][acol + 3][arow] = a4.w;
    *(float4*)&Bs[0][brow][bcol] = b4;
    __syncthreads();

    int tx = tid & 15, ty = tid >> 4;
    float acc[8][8];
#pragma unroll
    for (int i = 0; i < 8; ++i)
#pragma unroll
        for (int j = 0; j < 8; ++j) acc[i][j] = 0.0f;

    int buf = 0;
    for (int kt = 0; kt < 511; ++kt) {
        // prefetch next tile to registers (overlaps with compute below)
        a4 = *(const float4*)(Ap + (size_t)(kt + 1) * 8);
        b4 = *(const float4*)(Bp + (size_t)(kt + 1) * 8 * DIM);

#pragma unroll
        for (int k = 0; k < 8; ++k) {
            float a[8], b[8];
            *(float4*)&a[0] = *(const float4*)&As[buf][k][ty * 8];
            *(float4*)&a[4] = *(const float4*)&As[buf][k][ty * 8 + 4];
            *(float4*)&b[0] = *(const float4*)&Bs[buf][k][tx * 8];
            *(float4*)&b[4] = *(const float4*)&Bs[buf][k][tx * 8 + 4];
#pragma unroll
            for (int i = 0; i < 8; ++i)
#pragma unroll
                for (int j = 0; j < 8; ++j)
                    acc[i][j] = fmaf(a[i], b[j], acc[i][j]);
        }

        buf ^= 1;
        As[buf][acol + 0][arow] = a4.x;
        As[buf][acol + 1][arow] = a4.y;
        As[buf][acol + 2][arow] = a4.z;
        As[buf][acol + 3][arow] = a4.w;
        *(float4*)&Bs[buf][brow][bcol] = b4;
        __syncthreads();
    }
    // last tile
#pragma unroll
    for (int k = 0; k < 8; ++k) {
        float a[8], b[8];
        *(float4*)&a[0] = *(const float4*)&As[buf][k][ty * 8];
        *(float4*)&a[4] = *(const float4*)&As[buf][k][ty * 8 + 4];
        *(float4*)&b[0] = *(const float4*)&Bs[buf][k][tx * 8];
        *(float4*)&b[4] = *(const float4*)&Bs[buf][k][tx * 8 + 4];
#pragma unroll
        for (int i = 0; i < 8; ++i)
#pragma unroll
            for (int j = 0; j < 8; ++j)
                acc[i][j] = fmaf(a[i], b[j], acc[i][j]);
    }

    // epilogue: + bias, vectorized store
    const float* bp = bias + bn + tx * 8;
    float4 bb0 = *(const float4*)(bp);
    float4 bb1 = *(const float4*)(bp + 4);
#pragma unroll
    for (int i = 0; i < 8; ++i) {
        float* crow = C + (size_t)(bm + ty * 8 + i) * DIM + bn + tx * 8;
        float4 r0 = make_float4(acc[i][0] + bb0.x, acc[i][1] + bb0.y,
                                acc[i][2] + bb0.z, acc[i][3] + bb0.w);
        float4 r1 = make_float4(acc[i][4] + bb1.x, acc[i][5] + bb1.y,
                                acc[i][6] + bb1.z, acc[i][7] + bb1.w);
        *(float4*)crow = r0;
        *(float4*)(crow + 4) = r1;
    }
}

// ---------------------------------------------------------------------------
extern "C" void kernel_launch(void* const* d_in, const int* in_sizes, int n_in,
                              void* d_out, int out_size)
{
    const float* hidden      = (const float*)d_in[0];
    const float* slot_w      = (const float*)d_in[1];
    const float* slot_b      = (const float*)d_in[2];
    const float* leaf_logits = (const float*)d_in[3];
    const float* node_params = (const float*)d_in[4];
    const float* out_w       = (const float*)d_in[5];
    const float* out_b       = (const float*)d_in[6];
    float* out = (float*)d_out;

    slots_kernel<<<T_TOK, 128>>>(hidden, slot_w, slot_b);
    softmax_kernel<<<(NW * NLEAF + 255) / 256, 256>>>(leaf_logits);
    roots_kernel<<<dim3(NW / WPB, T_TOK / TPB), 256>>>(node_params);
    gemm_kernel<<<dim3(DIM / 128, T_TOK / 128), 256>>>(out_w, out_b, out);
}

// round 4
// speedup vs baseline: 3.1813x; 3.1813x over previous
#include <cuda_runtime.h>
#include <cuda_fp16.h>
#include <cstdint>
#include <cstddef>

// Shape: B=2,S=2048 -> T=4096 tokens, D=1024, W=4096, SLOT=8, 8 leaves.
#define T_TOK   4096
#define DIM     1024
#define NW      4096
#define NSLOT   8
#define NLEAF   8

// Scratch (device globals; no allocation allowed)
__device__ __align__(1024) float  g_slots[T_TOK * NSLOT];
__device__ __align__(1024) float  g_sel[NW * NLEAF * 9];
__device__ __align__(1024) __half g_roots_h[(size_t)T_TOK * NW];   // 32 MB
__device__ __align__(1024) __half g_outwT_h[(size_t)DIM * NW];     // 8 MB

// ---------------------------------------------------------------------------
__device__ __forceinline__ float tanh_fast(float x) {
    float ax = fabsf(x);
    float e  = __expf(-2.0f * ax);
    float r  = __fdividef(1.0f - e, 1.0f + e);
    return copysignf(r, x);
}

__device__ __forceinline__ uint32_t smem_u32(const void* p) {
    uint32_t a;
    asm("{ .reg .u64 t; cvta.to.shared.u64 t, %1; cvt.u32.u64 %0, t; }" : "=r"(a) : "l"(p));
    return a;
}

// ---------------------------------------------------------------------------
// Kernel A: slots = tanh(hidden @ slot_w + b). one block/token.
__global__ __launch_bounds__(128) void slots_kernel(
    const float* __restrict__ hidden,
    const float* __restrict__ slot_w,
    const float* __restrict__ slot_b)
{
    int t = blockIdx.x;
    const float* h = hidden + (size_t)t * DIM;
    float acc[NSLOT];
#pragma unroll
    for (int s = 0; s < NSLOT; ++s) acc[s] = 0.0f;

#pragma unroll
    for (int it = 0; it < 2; ++it) {
        int d = threadIdx.x * 4 + it * 512;
        float4 hv = *(const float4*)(h + d);
#pragma unroll
        for (int j = 0; j < 4; ++j) {
            float hx = (j == 0) ? hv.x : (j == 1) ? hv.y : (j == 2) ? hv.z : hv.w;
            const float* wr = slot_w + (size_t)(d + j) * NSLOT;
            float4 w0 = *(const float4*)(wr);
            float4 w1 = *(const float4*)(wr + 4);
            acc[0] = fmaf(hx, w0.x, acc[0]);
            acc[1] = fmaf(hx, w0.y, acc[1]);
            acc[2] = fmaf(hx, w0.z, acc[2]);
            acc[3] = fmaf(hx, w0.w, acc[3]);
            acc[4] = fmaf(hx, w1.x, acc[4]);
            acc[5] = fmaf(hx, w1.y, acc[5]);
            acc[6] = fmaf(hx, w1.z, acc[6]);
            acc[7] = fmaf(hx, w1.w, acc[7]);
        }
    }

#pragma unroll
    for (int s = 0; s < NSLOT; ++s) {
        float v = acc[s];
#pragma unroll
        for (int off = 16; off; off >>= 1)
            v += __shfl_xor_sync(0xffffffffu, v, off);
        acc[s] = v;
    }

    __shared__ float red[4][NSLOT];
    int lane = threadIdx.x & 31, warp = threadIdx.x >> 5;
    if (lane == 0) {
#pragma unroll
        for (int s = 0; s < NSLOT; ++s) red[warp][s] = acc[s];
    }
    __syncthreads();
    if (threadIdx.x < NSLOT) {
        int s = threadIdx.x;
        float v = red[0][s] + red[1][s] + red[2][s] + red[3][s] + slot_b[s];
        g_slots[(size_t)t * NSLOT + s] = tanhf(v);
    }
}

// ---------------------------------------------------------------------------
// Kernel B: softmax over 11 logits; keep sel[0..7] + folded bias (sel10-sel8)
__global__ __launch_bounds__(256) void softmax_kernel(const float* __restrict__ logits)
{
    int r = blockIdx.x * blockDim.x + threadIdx.x;
    if (r >= NW * NLEAF) return;
    const float* row = logits + (size_t)r * 11;
    float x[11];
    float m = -1e30f;
#pragma unroll
    for (int c = 0; c < 11; ++c) { x[c] = row[c]; m = fmaxf(m, x[c]); }
    float sum = 0.0f;
#pragma unroll
    for (int c = 0; c < 11; ++c) { x[c] = __expf(x[c] - m); sum += x[c]; }
    float inv = 1.0f / sum;
    float* o = g_sel + (size_t)r * 9;
#pragma unroll
    for (int c = 0; c < 8; ++c) o[c] = x[c] * inv;
    o[8] = (x[10] - x[8]) * inv;
}

// ---------------------------------------------------------------------------
// Kernel T: g_outwT_h[d][w] = half(out_w[w][d])
__global__ __launch_bounds__(256) void transpose_kernel(const float* __restrict__ Wm)
{
    __shared__ float t[32][33];
    int wt = blockIdx.x, dt = blockIdx.y;
    int tx = threadIdx.x & 31, ty = threadIdx.x >> 5;   // 32 x 8
#pragma unroll
    for (int i = 0; i < 4; ++i) {
        int w = wt * 32 + ty + i * 8;
        t[ty + i * 8][tx] = Wm[(size_t)w * DIM + dt * 32 + tx];
    }
    __syncthreads();
#pragma unroll
    for (int i = 0; i < 4; ++i) {
        int d = dt * 32 + ty + i * 8;
        g_outwT_h[(size_t)d * NW + wt * 32 + tx] = __float2half_rn(t[tx][ty + i * 8]);
    }
}

// ---------------------------------------------------------------------------
// Kernel C: fused leaf einsum + tree reduce (64 w x 16 tok per block)
#define WPB 64
#define TPB 16
__global__ __launch_bounds__(256) void roots_kernel(const float* __restrict__ node_params)
{
    __shared__ float s_sel[WPB * 73];
    __shared__ float s_slot[TPB][NSLOT];

    int w0 = blockIdx.x * WPB;
    int t0 = blockIdx.y * TPB;

    const float* gs = g_sel + (size_t)w0 * 72;
    for (int i = threadIdx.x; i < WPB * 72; i += 256) {
        int w = i / 72, j = i - w * 72;
        s_sel[w * 73 + j] = gs[i];
    }
    if (threadIdx.x < TPB * NSLOT) {
        int tt = threadIdx.x >> 3, c = threadIdx.x & 7;
        s_slot[tt][c] = g_slots[(size_t)(t0 + tt) * NSLOT + c];
    }
    __syncthreads();

    int wq = threadIdx.x & 63;
    int tg = threadIdx.x >> 6;

    float lw = node_params[0], rw = node_params[1], pw = node_params[2];
    float dw = node_params[3], nb = node_params[4];
    float la = lw + dw, ra = rw - dw;         // fold (L-R) term

    float slot[4][NSLOT];
#pragma unroll
    for (int t = 0; t < 4; ++t)
#pragma unroll
        for (int c = 0; c < NSLOT; ++c)
            slot[t][c] = s_slot[tg * 4 + t][c];

    const float* sel = s_sel + wq * 73;
    float v[4][NLEAF];
#pragma unroll
    for (int l = 0; l < NLEAF; ++l) {
        float bias = sel[l * 9 + 8];
        float v0 = bias, v1 = bias, v2 = bias, v3 = bias;
#pragma unroll
        for (int c = 0; c < 8; ++c) {
            float sc = sel[l * 9 + c];
            v0 = fmaf(sc, slot[0][c], v0);
            v1 = fmaf(sc, slot[1][c], v1);
            v2 = fmaf(sc, slot[2][c], v2);
            v3 = fmaf(sc, slot[3][c], v3);
        }
        v[0][l] = v0; v[1][l] = v1; v[2][l] = v2; v[3][l] = v3;
    }

#pragma unroll
    for (int t = 0; t < 4; ++t) {
        float* x = v[t];
#pragma unroll
        for (int d = 0; d < 3; ++d) {
            int n = NLEAF >> (d + 1);
#pragma unroll
            for (int i = 0; i < 8; ++i) {
                if (i < n) {
                    float L = x[2 * i], R = x[2 * i + 1];
                    float z = fmaf(la, L, nb);
                    z = fmaf(ra, R, z);
                    z = fmaf(pw, L * R, z);
                    x[i] = tanh_fast(z);
                }
            }
        }
    }

#pragma unroll
    for (int t = 0; t < 4; ++t) {
        int tok = t0 + tg * 4 + t;
        g_roots_h[(size_t)tok * NW + w0 + wq] = __float2half_rn(v[t][0]);
    }
}

// ---------------------------------------------------------------------------
// Kernel D: fp16 mma.sync GEMM.  out[t][d] = sum_w roots[t][w]*outwT[d][w] + b[d]
// A = g_roots_h [T][W] (row-major, K-contig), B = g_outwT_h [D][W] (K-contig ==
// col-major B for mma.row.col). 128x128x32 CTA tile, 3-stage cp.async (48KB,
// no smem attr needed), 8 warps each 32(M)x64(N).
#define BM 128
#define BN 128
#define BK 32
#define KTILES (NW / BK)            // 128
#define ASTG (BM * BK * 2)          // 8192 B
#define BSTG (BN * BK * 2)          // 8192 B
#define STG_BYTES (ASTG + BSTG)     // 16384 B
#define GSTAGES 3
#define GEMM_SMEM (GSTAGES * STG_BYTES)   // 49152 B = default dynamic limit

__device__ __forceinline__ void cp_async16(uint32_t dst, const void* src) {
    asm volatile("cp.async.cg.shared.global [%0], [%1], 16;" :: "r"(dst), "l"(src));
}

__global__ __launch_bounds__(256, 2) void gemm_mma_kernel(
    const float* __restrict__ bias, float* __restrict__ C)
{
    extern __shared__ char smem[];
    const uint32_t sbase = smem_u32(smem);

    const int tid  = threadIdx.x;
    const int lane = tid & 31;
    const int wid  = tid >> 5;
    const int warp_m = wid >> 1;        // 0..3  (32 rows each)
    const int warp_n = wid & 1;         // 0..1  (64 cols each)
    const int bm = blockIdx.y * BM;
    const int bn = blockIdx.x * BN;

    const __half* Ah = g_roots_h;
    const __half* Bh = g_outwT_h;

    // ---- cp.async source/dest precompute (2 A-chunks + 2 B-chunks / thread)
    // chunk id: row = id>>2 (0..127), c = id&3 (16B chunk within 64B row)
    uint32_t dA[2], dB[2];
    const __half* sA[2];
    const __half* sB[2];
#pragma unroll
    for (int j = 0; j < 2; ++j) {
        int id  = tid + 256 * j;
        int row = id >> 2, c = id & 3;
        int sw  = c ^ ((row >> 1) & 3);
        dA[j] = sbase + row * 64 + sw * 16;
        dB[j] = sbase + ASTG + row * 64 + sw * 16;
        sA[j] = Ah + (size_t)(bm + row) * NW + c * 8;
        sB[j] = Bh + (size_t)(bn + row) * NW + c * 8;
    }

    // ---- ldmatrix address precompute (byte offsets within a stage)
    // A: x4 covers m16 x k16. matrix = lane>>3: rowoff=(matrix&1)*8, kc=matrix>>1
    uint32_t offA[2][2];
#pragma unroll
    for (int mt = 0; mt < 2; ++mt)
#pragma unroll
        for (int ks = 0; ks < 2; ++ks) {
            int row = warp_m * 32 + mt * 16 + ((lane >> 3) & 1) * 8 + (lane & 7);
            int kc  = ks * 2 + (lane >> 4);
            offA[mt][ks] = row * 64 + ((kc ^ ((row >> 1) & 3)) * 16);
        }
    // B: x4 covers n16 x k16 (two n8 fragments). noff=(lane>>4)*8, kc=(lane>>3)&1
    uint32_t offB[4][2];
#pragma unroll
    for (int p = 0; p < 4; ++p)
#pragma unroll
        for (int ks = 0; ks < 2; ++ks) {
            int n  = warp_n * 64 + p * 16 + ((lane >> 4) & 1) * 8 + (lane & 7);
            int kc = ks * 2 + ((lane >> 3) & 1);
            offB[p][ks] = ASTG + n * 64 + ((kc ^ ((n >> 1) & 3)) * 16);
        }

    float acc[2][8][4];
#pragma unroll
    for (int mt = 0; mt < 2; ++mt)
#pragma unroll
        for (int nt = 0; nt < 8; ++nt)
#pragma unroll
            for (int i = 0; i < 4; ++i) acc[mt][nt][i] = 0.0f;

    // ---- prologue: stages 0..1
#pragma unroll
    for (int s = 0; s < GSTAGES - 1; ++s) {
#pragma unroll
        for (int j = 0; j < 2; ++j) {
            cp_async16(dA[j] + s * STG_BYTES, sA[j] + s * BK);
            cp_async16(dB[j] + s * STG_BYTES, sB[j] + s * BK);
        }
        asm volatile("cp.async.commit_group;" ::: "memory");
    }

    for (int kt = 0; kt < KTILES; ++kt) {
        asm volatile("cp.async.wait_group 1;" ::: "memory");
        __syncthreads();

        // issue loads for kt+2 into stage (kt+2)%3 (overwrites kt-1's stage; safe post-sync)
        if (kt + 2 < KTILES) {
            int s = (kt + 2) % 3;
#pragma unroll
            for (int j = 0; j < 2; ++j) {
                cp_async16(dA[j] + s * STG_BYTES, sA[j] + (size_t)(kt + 2) * BK);
                cp_async16(dB[j] + s * STG_BYTES, sB[j] + (size_t)(kt + 2) * BK);
            }
        }
        asm volatile("cp.async.commit_group;" ::: "memory");

        const uint32_t so = sbase + (kt % 3) * STG_BYTES;
#pragma unroll
        for (int ks = 0; ks < 2; ++ks) {
            uint32_t a[2][4], b[8][2];
#pragma unroll
            for (int mt = 0; mt < 2; ++mt)
                asm volatile("ldmatrix.sync.aligned.m8n8.x4.shared.b16 {%0,%1,%2,%3}, [%4];"
                             : "=r"(a[mt][0]), "=r"(a[mt][1]), "=r"(a[mt][2]), "=r"(a[mt][3])
                             : "r"(so + offA[mt][ks]));
#pragma unroll
            for (int p = 0; p < 4; ++p)
                asm volatile("ldmatrix.sync.aligned.m8n8.x4.shared.b16 {%0,%1,%2,%3}, [%4];"
                             : "=r"(b[2 * p][0]), "=r"(b[2 * p][1]),
                               "=r"(b[2 * p + 1][0]), "=r"(b[2 * p + 1][1])
                             : "r"(so + offB[p][ks]));
#pragma unroll
            for (int mt = 0; mt < 2; ++mt)
#pragma unroll
                for (int nt = 0; nt < 8; ++nt)
                    asm volatile(
                        "mma.sync.aligned.m16n8k16.row.col.f32.f16.f16.f32 "
                        "{%0,%1,%2,%3}, {%4,%5,%6,%7}, {%8,%9}, {%0,%1,%2,%3};"
                        : "+f"(acc[mt][nt][0]), "+f"(acc[mt][nt][1]),
                          "+f"(acc[mt][nt][2]), "+f"(acc[mt][nt][3])
                        : "r"(a[mt][0]), "r"(a[mt][1]), "r"(a[mt][2]), "r"(a[mt][3]),
                          "r"(b[nt][0]), "r"(b[nt][1]));
        }
    }

    // ---- epilogue: c0,c1 -> (row g, cols 2c..2c+1); c2,c3 -> (row g+8)
    const int g = lane >> 2, cq = lane & 3;
#pragma unroll
    for (int mt = 0; mt < 2; ++mt) {
        int r0 = bm + warp_m * 32 + mt * 16 + g;
#pragma unroll
        for (int nt = 0; nt < 8; ++nt) {
            int col = bn + warp_n * 64 + nt * 8 + 2 * cq;
            float2 bb = *(const float2*)(bias + col);
            float2 v0 = make_float2(acc[mt][nt][0] + bb.x, acc[mt][nt][1] + bb.y);
            float2 v1 = make_float2(acc[mt][nt][2] + bb.x, acc[mt][nt][3] + bb.y);
            *(float2*)(C + (size_t)r0 * DIM + col) = v0;
            *(float2*)(C + (size_t)(r0 + 8) * DIM + col) = v1;
        }
    }
}

// ---------------------------------------------------------------------------
extern "C" void kernel_launch(void* const* d_in, const int* in_sizes, int n_in,
                              void* d_out, int out_size)
{
    const float* hidden      = (const float*)d_in[0];
    const float* slot_w      = (const float*)d_in[1];
    const float* slot_b      = (const float*)d_in[2];
    const float* leaf_logits = (const float*)d_in[3];
    const float* node_params = (const float*)d_in[4];
    const float* out_w       = (const float*)d_in[5];
    const float* out_b       = (const float*)d_in[6];
    float* out = (float*)d_out;

    slots_kernel<<<T_TOK, 128>>>(hidden, slot_w, slot_b);
    softmax_kernel<<<(NW * NLEAF + 255) / 256, 256>>>(leaf_logits);
    transpose_kernel<<<dim3(NW / 32, DIM / 32), 256>>>(out_w);
    roots_kernel<<<dim3(NW / WPB, T_TOK / TPB), 256>>>(node_params);
    gemm_mma_kernel<<<dim3(DIM / BN, T_TOK / BM), 256, GEMM_SMEM>>>(out_b, out);
}

// round 8
// speedup vs baseline: 5.5105x; 1.7322x over previous
#include <cuda_runtime.h>
#include <cuda_fp16.h>
#include <cstdint>
#include <cstddef>

// Shape: B=2,S=2048 -> T=4096 tokens, D=1024, W=4096, SLOT=8, 8 leaves.
#define T_TOK   4096
#define DIM     1024
#define NW      4096
#define NSLOT   8
#define NLEAF   8

// Scratch (device globals; no allocation allowed)
__device__ __align__(1024) __half g_basis_h[(size_t)T_TOK * 16];      // slots,1,0...
__device__ __align__(1024) __half g_selB_h[(size_t)NLEAF * NW * 16];  // per-leaf sel rows
__device__ __align__(1024) __half g_roots_h[(size_t)T_TOK * NW];      // 32 MB
__device__ __align__(1024) __half g_outwT_h[(size_t)DIM * NW];        // 8 MB

// ---------------------------------------------------------------------------
__device__ __forceinline__ float tanh_exact(float x) {
    float ax = fabsf(x);
    float e  = __expf(-2.0f * ax);
    float r  = __fdividef(1.0f - e, 1.0f + e);
    return copysignf(r, x);
}
__device__ __forceinline__ float tanh_mufu(float x) {
    float y;
    asm("tanh.approx.f32 %0, %1;" : "=f"(y) : "f"(x));
    return y;
}
__device__ __forceinline__ uint32_t smem_u32(const void* p) {
    uint32_t a;
    asm("{ .reg .u64 t; cvta.to.shared.u64 t, %1; cvt.u32.u64 %0, t; }" : "=r"(a) : "l"(p));
    return a;
}

// ---------------------------------------------------------------------------
// Kernel A: basis[t] = [tanh(hidden@slot_w+b) (8), 1.0, 0 x7] as fp16.
__global__ __launch_bounds__(128) void slots_kernel(
    const float* __restrict__ hidden,
    const float* __restrict__ slot_w,
    const float* __restrict__ slot_b)
{
    int t = blockIdx.x;
    const float* h = hidden + (size_t)t * DIM;
    float acc[NSLOT];
#pragma unroll
    for (int s = 0; s < NSLOT; ++s) acc[s] = 0.0f;

#pragma unroll
    for (int it = 0; it < 2; ++it) {
        int d = threadIdx.x * 4 + it * 512;
        float4 hv = *(const float4*)(h + d);
#pragma unroll
        for (int j = 0; j < 4; ++j) {
            float hx = (j == 0) ? hv.x : (j == 1) ? hv.y : (j == 2) ? hv.z : hv.w;
            const float* wr = slot_w + (size_t)(d + j) * NSLOT;
            float4 w0 = *(const float4*)(wr);
            float4 w1 = *(const float4*)(wr + 4);
            acc[0] = fmaf(hx, w0.x, acc[0]);
            acc[1] = fmaf(hx, w0.y, acc[1]);
            acc[2] = fmaf(hx, w0.z, acc[2]);
            acc[3] = fmaf(hx, w0.w, acc[3]);
            acc[4] = fmaf(hx, w1.x, acc[4]);
            acc[5] = fmaf(hx, w1.y, acc[5]);
            acc[6] = fmaf(hx, w1.z, acc[6]);
            acc[7] = fmaf(hx, w1.w, acc[7]);
        }
    }

#pragma unroll
    for (int s = 0; s < NSLOT; ++s) {
        float v = acc[s];
#pragma unroll
        for (int off = 16; off; off >>= 1)
            v += __shfl_xor_sync(0xffffffffu, v, off);
        acc[s] = v;
    }

    __shared__ float red[4][NSLOT];
    int lane = threadIdx.x & 31, warp = threadIdx.x >> 5;
    if (lane == 0) {
#pragma unroll
        for (int s = 0; s < NSLOT; ++s) red[warp][s] = acc[s];
    }
    __syncthreads();
    if (threadIdx.x < 16) {
        int s = threadIdx.x;
        __half o;
        if (s < NSLOT) {
            float v = red[0][s] + red[1][s] + red[2][s] + red[3][s] + slot_b[s];
            o = __float2half_rn(tanhf(v));
        } else if (s == 8) {
            o = __float2half_rn(1.0f);
        } else {
            o = __float2half_rn(0.0f);
        }
        g_basis_h[(size_t)t * 16 + s] = o;
    }
}

// ---------------------------------------------------------------------------
// Kernel B: softmax over 11 logits -> g_selB_h[l][w][16] fp16:
// [sel0..sel7, sel10-sel8, 0 x7]  (basis consts are -1,0,1)
__global__ __launch_bounds__(256) void softmax_kernel(const float* __restrict__ logits)
{
    int r = blockIdx.x * blockDim.x + threadIdx.x;   // w*8 + l
    if (r >= NW * NLEAF) return;
    int w = r >> 3, l = r & 7;
    const float* row = logits + (size_t)r * 11;
    float x[11];
    float m = -1e30f;
#pragma unroll
    for (int c = 0; c < 11; ++c) { x[c] = row[c]; m = fmaxf(m, x[c]); }
    float sum = 0.0f;
#pragma unroll
    for (int c = 0; c < 11; ++c) { x[c] = __expf(x[c] - m); sum += x[c]; }
    float inv = 1.0f / sum;

    __half2* dst = (__half2*)(g_selB_h + ((size_t)l * NW + w) * 16);
#pragma unroll
    for (int c = 0; c < 4; ++c)
        dst[c] = __floats2half2_rn(x[2 * c] * inv, x[2 * c + 1] * inv);
    dst[4] = __floats2half2_rn((x[10] - x[8]) * inv, 0.0f);
    __half2 z = __floats2half2_rn(0.0f, 0.0f);
    dst[5] = z; dst[6] = z; dst[7] = z;
}

// ---------------------------------------------------------------------------
// Kernel T: g_outwT_h[d][w] = half(out_w[w][d])
__global__ __launch_bounds__(256) void transpose_kernel(const float* __restrict__ Wm)
{
    __shared__ float t[32][33];
    int wt = blockIdx.x, dt = blockIdx.y;
    int tx = threadIdx.x & 31, ty = threadIdx.x >> 5;   // 32 x 8
#pragma unroll
    for (int i = 0; i < 4; ++i) {
        int w = wt * 32 + ty + i * 8;
        t[ty + i * 8][tx] = Wm[(size_t)w * DIM + dt * 32 + tx];
    }
    __syncthreads();
#pragma unroll
    for (int i = 0; i < 4; ++i) {
        int d = dt * 32 + ty + i * 8;
        g_outwT_h[(size_t)d * NW + wt * 32 + tx] = __float2half_rn(t[tx][ty + i * 8]);
    }
}

// ---------------------------------------------------------------------------
// Kernel C: leaf einsum via mma.sync (K=16) + tree reduce in registers.
// CTA: 32 tokens x 64 w, 8 warps, warp tile 16 tok x 16 w.
// Per warp: 1 A ldmatrix.x4 + 8 B ldmatrix.x4 (one per leaf) + 16 MMAs.
// Each thread ends with 8 (token,w) positions x 8 leaves in accumulators.
__global__ __launch_bounds__(256) void roots_mma_kernel(const float* __restrict__ node_params)
{
    __shared__ __align__(16) char sAraw[32 * 32];          // 32 tok rows x 32B
    __shared__ __align__(16) char sBraw[8 * 64 * 32];      // [leaf][w] rows x 32B

    const int tid  = threadIdx.x;
    const int lane = tid & 31;
    const int wid  = tid >> 5;
    const int warp_m = wid & 1;         // token tile (16 each)
    const int warp_n = wid >> 1;        // w tile (16 each)
    const int bt = blockIdx.y * 32;
    const int bw = blockIdx.x * 64;

    const uint32_t uA = smem_u32(sAraw);
    const uint32_t uB = smem_u32(sBraw);

    // ---- fill sA: 64 chunks of 16B, swizzle c ^ ((row>>2)&1)
    if (tid < 64) {
        int row = tid >> 1, c = tid & 1;
        const uint4 v = *(const uint4*)(g_basis_h + (size_t)(bt + row) * 16 + c * 8);
        *(uint4*)(sAraw + row * 32 + ((c ^ ((row >> 2) & 1)) << 4)) = v;
    }
    // ---- fill sB: 1024 chunks, 4 per thread
#pragma unroll
    for (int j = 0; j < 4; ++j) {
        int id = tid + 256 * j;
        int l = id >> 7, w = (id >> 1) & 63, c = id & 1;
        const uint4 v = *(const uint4*)(g_selB_h + ((size_t)l * NW + bw + w) * 16 + c * 8);
        *(uint4*)(sBraw + l * 2048 + w * 32 + ((c ^ ((w >> 2) & 1)) << 4)) = v;
    }
    __syncthreads();

    // ---- A fragment (m16 x k16)
    uint32_t a[4];
    {
        int row = warp_m * 16 + ((lane >> 3) & 1) * 8 + (lane & 7);
        int kc  = lane >> 4;
        uint32_t addr = uA + row * 32 + ((kc ^ ((row >> 2) & 1)) << 4);
        asm volatile("ldmatrix.sync.aligned.m8n8.x4.shared.b16 {%0,%1,%2,%3}, [%4];"
                     : "=r"(a[0]), "=r"(a[1]), "=r"(a[2]), "=r"(a[3]) : "r"(addr));
    }

    float acc[2][8][4];
#pragma unroll
    for (int nt = 0; nt < 2; ++nt)
#pragma unroll
        for (int l = 0; l < 8; ++l)
#pragma unroll
            for (int i = 0; i < 4; ++i) acc[nt][l][i] = 0.0f;

    // ---- per-leaf B fragment + 2 MMAs
    {
        int n  = warp_n * 16 + ((lane >> 4) & 1) * 8 + (lane & 7);
        int kc = (lane >> 3) & 1;
        uint32_t baddr = uB + n * 32 + ((kc ^ ((n >> 2) & 1)) << 4);
#pragma unroll
        for (int l = 0; l < 8; ++l) {
            uint32_t b0, b1, b2, b3;
            asm volatile("ldmatrix.sync.aligned.m8n8.x4.shared.b16 {%0,%1,%2,%3}, [%4];"
                         : "=r"(b0), "=r"(b1), "=r"(b2), "=r"(b3)
                         : "r"(baddr + l * 2048));
            asm volatile(
                "mma.sync.aligned.m16n8k16.row.col.f32.f16.f16.f32 "
                "{%0,%1,%2,%3}, {%4,%5,%6,%7}, {%8,%9}, {%0,%1,%2,%3};"
                : "+f"(acc[0][l][0]), "+f"(acc[0][l][1]), "+f"(acc[0][l][2]), "+f"(acc[0][l][3])
                : "r"(a[0]), "r"(a[1]), "r"(a[2]), "r"(a[3]), "r"(b0), "r"(b1));
            asm volatile(
                "mma.sync.aligned.m16n8k16.row.col.f32.f16.f16.f32 "
                "{%0,%1,%2,%3}, {%4,%5,%6,%7}, {%8,%9}, {%0,%1,%2,%3};"
                : "+f"(acc[1][l][0]), "+f"(acc[1][l][1]), "+f"(acc[1][l][2]), "+f"(acc[1][l][3])
                : "r"(a[0]), "r"(a[1]), "r"(a[2]), "r"(a[3]), "r"(b2), "r"(b3));
        }
    }

    // ---- tree reduce per (token,w) position
    float lw = __ldg(node_params + 0), rw = __ldg(node_params + 1);
    float pw = __ldg(node_params + 2), dw = __ldg(node_params + 3);
    float nb = __ldg(node_params + 4);
    float la = lw + dw, ra = rw - dw;

    const int g = lane >> 2, cq = lane & 3;

#pragma unroll
    for (int nt = 0; nt < 2; ++nt) {
        float roots[4];
#pragma unroll
        for (int ci = 0; ci < 4; ++ci) {
            float x[8];
#pragma unroll
            for (int l = 0; l < 8; ++l) x[l] = acc[nt][l][ci];
            // depth 0: 4 nodes (MUFU tanh)
#pragma unroll
            for (int i = 0; i < 4; ++i) {
                float L = x[2 * i], R = x[2 * i + 1];
                x[i] = tanh_mufu(fmaf(la, L, fmaf(ra, R, fmaf(pw, L * R, nb))));
            }
            // depth 1: 2 nodes (MUFU tanh)
#pragma unroll
            for (int i = 0; i < 2; ++i) {
                float L = x[2 * i], R = x[2 * i + 1];
                x[i] = tanh_mufu(fmaf(la, L, fmaf(ra, R, fmaf(pw, L * R, nb))));
            }
            // depth 2 (root): exact tanh
            {
                float L = x[0], R = x[1];
                roots[ci] = tanh_exact(fmaf(la, L, fmaf(ra, R, fmaf(pw, L * R, nb))));
            }
        }
        int col = bw + warp_n * 16 + nt * 8 + 2 * cq;
        int r0  = bt + warp_m * 16 + g;
        *(__half2*)(g_roots_h + (size_t)r0 * NW + col)       = __floats2half2_rn(roots[0], roots[1]);
        *(__half2*)(g_roots_h + (size_t)(r0 + 8) * NW + col) = __floats2half2_rn(roots[2], roots[3]);
    }
}

// ---------------------------------------------------------------------------
// Kernel D: fp16 mma.sync GEMM (unchanged from R4, passing).
#define BM 128
#define BN 128
#define BK 32
#define KTILES (NW / BK)
#define ASTG (BM * BK * 2)
#define BSTG (BN * BK * 2)
#define STG_BYTES (ASTG + BSTG)
#define GSTAGES 3
#define GEMM_SMEM (GSTAGES * STG_BYTES)   // 49152 B

__device__ __forceinline__ void cp_async16(uint32_t dst, const void* src) {
    asm volatile("cp.async.cg.shared.global [%0], [%1], 16;" :: "r"(dst), "l"(src));
}

__global__ __launch_bounds__(256, 2) void gemm_mma_kernel(
    const float* __restrict__ bias, float* __restrict__ C)
{
    extern __shared__ char smem[];
    const uint32_t sbase = smem_u32(smem);

    const int tid  = threadIdx.x;
    const int lane = tid & 31;
    const int wid  = tid >> 5;
    const int warp_m = wid >> 1;
    const int warp_n = wid & 1;
    const int bm = blockIdx.y * BM;
    const int bn = blockIdx.x * BN;

    const __half* Ah = g_roots_h;
    const __half* Bh = g_outwT_h;

    uint32_t dA[2], dB[2];
    const __half* sA[2];
    const __half* sB[2];
#pragma unroll
    for (int j = 0; j < 2; ++j) {
        int id  = tid + 256 * j;
        int row = id >> 2, c = id & 3;
        int sw  = c ^ ((row >> 1) & 3);
        dA[j] = sbase + row * 64 + sw * 16;
        dB[j] = sbase + ASTG + row * 64 + sw * 16;
        sA[j] = Ah + (size_t)(bm + row) * NW + c * 8;
        sB[j] = Bh + (size_t)(bn + row) * NW + c * 8;
    }

    uint32_t offA[2][2];
#pragma unroll
    for (int mt = 0; mt < 2; ++mt)
#pragma unroll
        for (int ks = 0; ks < 2; ++ks) {
            int row = warp_m * 32 + mt * 16 + ((lane >> 3) & 1) * 8 + (lane & 7);
            int kc  = ks * 2 + (lane >> 4);
            offA[mt][ks] = row * 64 + ((kc ^ ((row >> 1) & 3)) * 16);
        }
    uint32_t offB[4][2];
#pragma unroll
    for (int p = 0; p < 4; ++p)
#pragma unroll
        for (int ks = 0; ks < 2; ++ks) {
            int n  = warp_n * 64 + p * 16 + ((lane >> 4) & 1) * 8 + (lane & 7);
            int kc = ks * 2 + ((lane >> 3) & 1);
            offB[p][ks] = ASTG + n * 64 + ((kc ^ ((n >> 1) & 3)) * 16);
        }

    float acc[2][8][4];
#pragma unroll
    for (int mt = 0; mt < 2; ++mt)
#pragma unroll
        for (int nt = 0; nt < 8; ++nt)
#pragma unroll
            for (int i = 0; i < 4; ++i) acc[mt][nt][i] = 0.0f;

#pragma unroll
    for (int s = 0; s < GSTAGES - 1; ++s) {
#pragma unroll
        for (int j = 0; j < 2; ++j) {
            cp_async16(dA[j] + s * STG_BYTES, sA[j] + s * BK);
            cp_async16(dB[j] + s * STG_BYTES, sB[j] + s * BK);
        }
        asm volatile("cp.async.commit_group;" ::: "memory");
    }

    for (int kt = 0; kt < KTILES; ++kt) {
        asm volatile("cp.async.wait_group 1;" ::: "memory");
        __syncthreads();

        if (kt + 2 < KTILES) {
            int s = (kt + 2) % 3;
#pragma unroll
            for (int j = 0; j < 2; ++j) {
                cp_async16(dA[j] + s * STG_BYTES, sA[j] + (size_t)(kt + 2) * BK);
                cp_async16(dB[j] + s * STG_BYTES, sB[j] + (size_t)(kt + 2) * BK);
            }
        }
        asm volatile("cp.async.commit_group;" ::: "memory");

        const uint32_t so = sbase + (kt % 3) * STG_BYTES;
#pragma unroll
        for (int ks = 0; ks < 2; ++ks) {
            uint32_t a[2][4], b[8][2];
#pragma unroll
            for (int mt = 0; mt < 2; ++mt)
                asm volatile("ldmatrix.sync.aligned.m8n8.x4.shared.b16 {%0,%1,%2,%3}, [%4];"
                             : "=r"(a[mt][0]), "=r"(a[mt][1]), "=r"(a[mt][2]), "=r"(a[mt][3])
                             : "r"(so + offA[mt][ks]));
#pragma unroll
            for (int p = 0; p < 4; ++p)
                asm volatile("ldmatrix.sync.aligned.m8n8.x4.shared.b16 {%0,%1,%2,%3}, [%4];"
                             : "=r"(b[2 * p][0]), "=r"(b[2 * p][1]),
                               "=r"(b[2 * p + 1][0]), "=r"(b[2 * p + 1][1])
                             : "r"(so + offB[p][ks]));
#pragma unroll
            for (int mt = 0; mt < 2; ++mt)
#pragma unroll
                for (int nt = 0; nt < 8; ++nt)
                    asm volatile(
                        "mma.sync.aligned.m16n8k16.row.col.f32.f16.f16.f32 "
                        "{%0,%1,%2,%3}, {%4,%5,%6,%7}, {%8,%9}, {%0,%1,%2,%3};"
                        : "+f"(acc[mt][nt][0]), "+f"(acc[mt][nt][1]),
                          "+f"(acc[mt][nt][2]), "+f"(acc[mt][nt][3])
                        : "r"(a[mt][0]), "r"(a[mt][1]), "r"(a[mt][2]), "r"(a[mt][3]),
                          "r"(b[nt][0]), "r"(b[nt][1]));
        }
    }

    const int g = lane >> 2, cq = lane & 3;
#pragma unroll
    for (int mt = 0; mt < 2; ++mt) {
        int r0 = bm + warp_m * 32 + mt * 16 + g;
#pragma unroll
        for (int nt = 0; nt < 8; ++nt) {
            int col = bn + warp_n * 64 + nt * 8 + 2 * cq;
            float2 bb = *(const float2*)(bias + col);
            float2 v0 = make_float2(acc[mt][nt][0] + bb.x, acc[mt][nt][1] + bb.y);
            float2 v1 = make_float2(acc[mt][nt][2] + bb.x, acc[mt][nt][3] + bb.y);
            *(float2*)(C + (size_t)r0 * DIM + col) = v0;
            *(float2*)(C + (size_t)(r0 + 8) * DIM + col) = v1;
        }
    }
}

// ---------------------------------------------------------------------------
extern "C" void kernel_launch(void* const* d_in, const int* in_sizes, int n_in,
                              void* d_out, int out_size)
{
    const float* hidden      = (const float*)d_in[0];
    const float* slot_w      = (const float*)d_in[1];
    const float* slot_b      = (const float*)d_in[2];
    const float* leaf_logits = (const float*)d_in[3];
    const float* node_params = (const float*)d_in[4];
    const float* out_w       = (const float*)d_in[5];
    const float* out_b       = (const float*)d_in[6];
    float* out = (float*)d_out;

    slots_kernel<<<T_TOK, 128>>>(hidden, slot_w, slot_b);
    softmax_kernel<<<(NW * NLEAF + 255) / 256, 256>>>(leaf_logits);
    transpose_kernel<<<dim3(NW / 32, DIM / 32), 256>>>(out_w);
    roots_mma_kernel<<<dim3(NW / 64, T_TOK / 32), 256>>>(node_params);
    gemm_mma_kernel<<<dim3(DIM / BN, T_TOK / BM), 256, GEMM_SMEM>>>(out_b, out);
}

// round 9
// speedup vs baseline: 5.8280x; 1.0576x over previous
#include <cuda_runtime.h>
#include <cuda_fp16.h>
#include <cstdint>
#include <cstddef>

// Shape: B=2,S=2048 -> T=4096 tokens, D=1024, W=4096, SLOT=8, 8 leaves.
#define T_TOK   4096
#define DIM     1024
#define NW      4096
#define NSLOT   8
#define NLEAF   8

// Scratch (device globals; no allocation allowed)
__device__ __align__(1024) __half g_basis_h[(size_t)T_TOK * 16];      // slots,1,0...
__device__ __align__(1024) __half g_selB_h[(size_t)NLEAF * NW * 16];  // per-leaf sel rows
__device__ __align__(1024) __half g_roots_h[(size_t)T_TOK * NW];      // 32 MB
__device__ __align__(1024) __half g_outwT_h[(size_t)DIM * NW];        // 8 MB

// ---------------------------------------------------------------------------
__device__ __forceinline__ float tanh_mufu(float x) {
    float y;
    asm("tanh.approx.f32 %0, %1;" : "=f"(y) : "f"(x));
    return y;
}
__device__ __forceinline__ uint32_t smem_u32(const void* p) {
    uint32_t a;
    asm("{ .reg .u64 t; cvta.to.shared.u64 t, %1; cvt.u32.u64 %0, t; }" : "=r"(a) : "l"(p));
    return a;
}

// ---------------------------------------------------------------------------
// Kernel A: basis[t] = [tanh(hidden@slot_w+b) (8), 1.0, 0 x7] as fp16.
__global__ __launch_bounds__(128) void slots_kernel(
    const float* __restrict__ hidden,
    const float* __restrict__ slot_w,
    const float* __restrict__ slot_b)
{
    int t = blockIdx.x;
    const float* h = hidden + (size_t)t * DIM;
    float acc[NSLOT];
#pragma unroll
    for (int s = 0; s < NSLOT; ++s) acc[s] = 0.0f;

#pragma unroll
    for (int it = 0; it < 2; ++it) {
        int d = threadIdx.x * 4 + it * 512;
        float4 hv = *(const float4*)(h + d);
#pragma unroll
        for (int j = 0; j < 4; ++j) {
            float hx = (j == 0) ? hv.x : (j == 1) ? hv.y : (j == 2) ? hv.z : hv.w;
            const float* wr = slot_w + (size_t)(d + j) * NSLOT;
            float4 w0 = *(const float4*)(wr);
            float4 w1 = *(const float4*)(wr + 4);
            acc[0] = fmaf(hx, w0.x, acc[0]);
            acc[1] = fmaf(hx, w0.y, acc[1]);
            acc[2] = fmaf(hx, w0.z, acc[2]);
            acc[3] = fmaf(hx, w0.w, acc[3]);
            acc[4] = fmaf(hx, w1.x, acc[4]);
            acc[5] = fmaf(hx, w1.y, acc[5]);
            acc[6] = fmaf(hx, w1.z, acc[6]);
            acc[7] = fmaf(hx, w1.w, acc[7]);
        }
    }

#pragma unroll
    for (int s = 0; s < NSLOT; ++s) {
        float v = acc[s];
#pragma unroll
        for (int off = 16; off; off >>= 1)
            v += __shfl_xor_sync(0xffffffffu, v, off);
        acc[s] = v;
    }

    __shared__ float red[4][NSLOT];
    int lane = threadIdx.x & 31, warp = threadIdx.x >> 5;
    if (lane == 0) {
#pragma unroll
        for (int s = 0; s < NSLOT; ++s) red[warp][s] = acc[s];
    }
    __syncthreads();
    if (threadIdx.x < 16) {
        int s = threadIdx.x;
        __half o;
        if (s < NSLOT) {
            float v = red[0][s] + red[1][s] + red[2][s] + red[3][s] + slot_b[s];
            o = __float2half_rn(tanhf(v));
        } else if (s == 8) {
            o = __float2half_rn(1.0f);
        } else {
            o = __float2half_rn(0.0f);
        }
        g_basis_h[(size_t)t * 16 + s] = o;
    }
}

// ---------------------------------------------------------------------------
// Kernel B: softmax over 11 logits -> g_selB_h[l][w][16] fp16:
// [sel0..sel7, sel10-sel8, 0 x7]  (basis consts are -1,0,1)
__global__ __launch_bounds__(256) void softmax_kernel(const float* __restrict__ logits)
{
    int r = blockIdx.x * blockDim.x + threadIdx.x;   // w*8 + l
    if (r >= NW * NLEAF) return;
    int w = r >> 3, l = r & 7;
    const float* row = logits + (size_t)r * 11;
    float x[11];
    float m = -1e30f;
#pragma unroll
    for (int c = 0; c < 11; ++c) { x[c] = row[c]; m = fmaxf(m, x[c]); }
    float sum = 0.0f;
#pragma unroll
    for (int c = 0; c < 11; ++c) { x[c] = __expf(x[c] - m); sum += x[c]; }
    float inv = 1.0f / sum;

    __half2* dst = (__half2*)(g_selB_h + ((size_t)l * NW + w) * 16);
#pragma unroll
    for (int c = 0; c < 4; ++c)
        dst[c] = __floats2half2_rn(x[2 * c] * inv, x[2 * c + 1] * inv);
    dst[4] = __floats2half2_rn((x[10] - x[8]) * inv, 0.0f);
    __half2 z = __floats2half2_rn(0.0f, 0.0f);
    dst[5] = z; dst[6] = z; dst[7] = z;
}

// ---------------------------------------------------------------------------
// Kernel T: g_outwT_h[d][w] = half(out_w[w][d])
__global__ __launch_bounds__(256) void transpose_kernel(const float* __restrict__ Wm)
{
    __shared__ float t[32][33];
    int wt = blockIdx.x, dt = blockIdx.y;
    int tx = threadIdx.x & 31, ty = threadIdx.x >> 5;   // 32 x 8
#pragma unroll
    for (int i = 0; i < 4; ++i) {
        int w = wt * 32 + ty + i * 8;
        t[ty + i * 8][tx] = Wm[(size_t)w * DIM + dt * 32 + tx];
    }
    __syncthreads();
#pragma unroll
    for (int i = 0; i < 4; ++i) {
        int d = dt * 32 + ty + i * 8;
        g_outwT_h[(size_t)d * NW + wt * 32 + tx] = __float2half_rn(t[tx][ty + i * 8]);
    }
}

// ---------------------------------------------------------------------------
// Kernel C: leaf einsum via mma.sync (K=16) + tree reduce in registers.
// CTA: 32 tokens x 64 w, 8 warps, warp tile 16 tok x 16 w.
__global__ __launch_bounds__(256) void roots_mma_kernel(const float* __restrict__ node_params)
{
    __shared__ __align__(16) char sAraw[32 * 32];          // 32 tok rows x 32B
    __shared__ __align__(16) char sBraw[8 * 64 * 32];      // [leaf][w] rows x 32B

    const int tid  = threadIdx.x;
    const int lane = tid & 31;
    const int wid  = tid >> 5;
    const int warp_m = wid & 1;         // token tile (16 each)
    const int warp_n = wid >> 1;        // w tile (16 each)
    const int bt = blockIdx.y * 32;
    const int bw = blockIdx.x * 64;

    const uint32_t uA = smem_u32(sAraw);
    const uint32_t uB = smem_u32(sBraw);

    // ---- fill sA: 64 chunks of 16B, swizzle c ^ ((row>>2)&1)
    if (tid < 64) {
        int row = tid >> 1, c = tid & 1;
        const uint4 v = *(const uint4*)(g_basis_h + (size_t)(bt + row) * 16 + c * 8);
        *(uint4*)(sAraw + row * 32 + ((c ^ ((row >> 2) & 1)) << 4)) = v;
    }
    // ---- fill sB: 1024 chunks, 4 per thread
#pragma unroll
    for (int j = 0; j < 4; ++j) {
        int id = tid + 256 * j;
        int l = id >> 7, w = (id >> 1) & 63, c = id & 1;
        const uint4 v = *(const uint4*)(g_selB_h + ((size_t)l * NW + bw + w) * 16 + c * 8);
        *(uint4*)(sBraw + l * 2048 + w * 32 + ((c ^ ((w >> 2) & 1)) << 4)) = v;
    }
    __syncthreads();

    // ---- A fragment (m16 x k16)
    uint32_t a[4];
    {
        int row = warp_m * 16 + ((lane >> 3) & 1) * 8 + (lane & 7);
        int kc  = lane >> 4;
        uint32_t addr = uA + row * 32 + ((kc ^ ((row >> 2) & 1)) << 4);
        asm volatile("ldmatrix.sync.aligned.m8n8.x4.shared.b16 {%0,%1,%2,%3}, [%4];"
                     : "=r"(a[0]), "=r"(a[1]), "=r"(a[2]), "=r"(a[3]) : "r"(addr));
    }

    float acc[2][8][4];
#pragma unroll
    for (int nt = 0; nt < 2; ++nt)
#pragma unroll
        for (int l = 0; l < 8; ++l)
#pragma unroll
            for (int i = 0; i < 4; ++i) acc[nt][l][i] = 0.0f;

    // ---- per-leaf B fragment + 2 MMAs
    {
        int n  = warp_n * 16 + ((lane >> 4) & 1) * 8 + (lane & 7);
        int kc = (lane >> 3) & 1;
        uint32_t baddr = uB + n * 32 + ((kc ^ ((n >> 2) & 1)) << 4);
#pragma unroll
        for (int l = 0; l < 8; ++l) {
            uint32_t b0, b1, b2, b3;
            asm volatile("ldmatrix.sync.aligned.m8n8.x4.shared.b16 {%0,%1,%2,%3}, [%4];"
                         : "=r"(b0), "=r"(b1), "=r"(b2), "=r"(b3)
                         : "r"(baddr + l * 2048));
            asm volatile(
                "mma.sync.aligned.m16n8k16.row.col.f32.f16.f16.f32 "
                "{%0,%1,%2,%3}, {%4,%5,%6,%7}, {%8,%9}, {%0,%1,%2,%3};"
                : "+f"(acc[0][l][0]), "+f"(acc[0][l][1]), "+f"(acc[0][l][2]), "+f"(acc[0][l][3])
                : "r"(a[0]), "r"(a[1]), "r"(a[2]), "r"(a[3]), "r"(b0), "r"(b1));
            asm volatile(
                "mma.sync.aligned.m16n8k16.row.col.f32.f16.f16.f32 "
                "{%0,%1,%2,%3}, {%4,%5,%6,%7}, {%8,%9}, {%0,%1,%2,%3};"
                : "+f"(acc[1][l][0]), "+f"(acc[1][l][1]), "+f"(acc[1][l][2]), "+f"(acc[1][l][3])
                : "r"(a[0]), "r"(a[1]), "r"(a[2]), "r"(a[3]), "r"(b2), "r"(b3));
        }
    }

    // ---- tree reduce per (token,w) position (3 FMA + 1 MUFU per node)
    float lw = __ldg(node_params + 0), rw = __ldg(node_params + 1);
    float pw = __ldg(node_params + 2), dw = __ldg(node_params + 3);
    float nb = __ldg(node_params + 4);
    float la = lw + dw, ra = rw - dw;

    const int g = lane >> 2, cq = lane & 3;

#pragma unroll
    for (int nt = 0; nt < 2; ++nt) {
        float roots[4];
#pragma unroll
        for (int ci = 0; ci < 4; ++ci) {
            float x[8];
#pragma unroll
            for (int l = 0; l < 8; ++l) x[l] = acc[nt][l][ci];
#pragma unroll
            for (int d = 0; d < 3; ++d) {
                int n = NLEAF >> (d + 1);
#pragma unroll
                for (int i = 0; i < 4; ++i) {
                    if (i < n) {
                        float L = x[2 * i], R = x[2 * i + 1];
                        // z = la*L + ra*R + pw*L*R + nb = L*(pw*R+la) + (ra*R+nb)
                        x[i] = tanh_mufu(fmaf(L, fmaf(pw, R, la), fmaf(ra, R, nb)));
                    }
                }
            }
            roots[ci] = x[0];
        }
        int col = bw + warp_n * 16 + nt * 8 + 2 * cq;
        int r0  = bt + warp_m * 16 + g;
        *(__half2*)(g_roots_h + (size_t)r0 * NW + col)       = __floats2half2_rn(roots[0], roots[1]);
        *(__half2*)(g_roots_h + (size_t)(r0 + 8) * NW + col) = __floats2half2_rn(roots[2], roots[3]);
    }
}

// ---------------------------------------------------------------------------
// Kernel D: fp16 mma.sync GEMM, BK=64 (3 stages x 32KB = 96KB smem).
// A = g_roots_h [T][W], B = g_outwT_h [D][W] (both K-contig).
// 128x128x64 CTA tile, 8 warps each 32(M)x64(N). Row = 128B (8 x 16B chunks),
// swizzle chunk ^= (row & 7).
#define BM 128
#define BN 128
#define BK 64
#define KTILES (NW / BK)                  // 64
#define ROWB (BK * 2)                     // 128 bytes/row
#define ASTG (BM * ROWB)                  // 16384
#define BSTG (BN * ROWB)                  // 16384
#define STG_BYTES (ASTG + BSTG)           // 32768
#define GSTAGES 3
#define GEMM_SMEM (GSTAGES * STG_BYTES)   // 98304

__device__ __forceinline__ void cp_async16(uint32_t dst, const void* src) {
    asm volatile("cp.async.cg.shared.global [%0], [%1], 16;" :: "r"(dst), "l"(src));
}

__global__ __launch_bounds__(256, 2) void gemm_mma_kernel(
    const float* __restrict__ bias, float* __restrict__ C)
{
    extern __shared__ char smem[];
    const uint32_t sbase = smem_u32(smem);

    const int tid  = threadIdx.x;
    const int lane = tid & 31;
    const int wid  = tid >> 5;
    const int warp_m = wid >> 1;
    const int warp_n = wid & 1;
    const int bm = blockIdx.y * BM;
    const int bn = blockIdx.x * BN;

    const __half* Ah = g_roots_h;
    const __half* Bh = g_outwT_h;

    // ---- cp.async: 4 A-chunks + 4 B-chunks per thread (id = tid + 256j)
    uint32_t dA[4], dB[4];
    const __half* sA[4];
    const __half* sB[4];
#pragma unroll
    for (int j = 0; j < 4; ++j) {
        int id  = tid + 256 * j;          // 0..1023
        int row = id >> 3, c = id & 7;
        int sw  = c ^ (row & 7);
        dA[j] = sbase + row * ROWB + sw * 16;
        dB[j] = sbase + ASTG + row * ROWB + sw * 16;
        sA[j] = Ah + (size_t)(bm + row) * NW + c * 8;
        sB[j] = Bh + (size_t)(bn + row) * NW + c * 8;
    }

    // ---- ldmatrix offsets (per ks = 0..3 k16-steps)
    uint32_t offA[2][4];
#pragma unroll
    for (int mt = 0; mt < 2; ++mt)
#pragma unroll
        for (int ks = 0; ks < 4; ++ks) {
            int row = warp_m * 32 + mt * 16 + ((lane >> 3) & 1) * 8 + (lane & 7);
            int kc  = ks * 2 + (lane >> 4);
            offA[mt][ks] = row * ROWB + ((kc ^ (row & 7)) * 16);
        }
    uint32_t offB[4][4];
#pragma unroll
    for (int p = 0; p < 4; ++p)
#pragma unroll
        for (int ks = 0; ks < 4; ++ks) {
            int n  = warp_n * 64 + p * 16 + ((lane >> 4) & 1) * 8 + (lane & 7);
            int kc = ks * 2 + ((lane >> 3) & 1);
            offB[p][ks] = ASTG + n * ROWB + ((kc ^ (n & 7)) * 16);
        }

    float acc[2][8][4];
#pragma unroll
    for (int mt = 0; mt < 2; ++mt)
#pragma unroll
        for (int nt = 0; nt < 8; ++nt)
#pragma unroll
            for (int i = 0; i < 4; ++i) acc[mt][nt][i] = 0.0f;

    // ---- prologue: stages 0..1
#pragma unroll
    for (int s = 0; s < GSTAGES - 1; ++s) {
#pragma unroll
        for (int j = 0; j < 4; ++j) {
            cp_async16(dA[j] + s * STG_BYTES, sA[j] + s * BK);
            cp_async16(dB[j] + s * STG_BYTES, sB[j] + s * BK);
        }
        asm volatile("cp.async.commit_group;" ::: "memory");
    }

    for (int kt = 0; kt < KTILES; ++kt) {
        asm volatile("cp.async.wait_group 1;" ::: "memory");
        __syncthreads();

        if (kt + 2 < KTILES) {
            int s = (kt + 2) % 3;
#pragma unroll
            for (int j = 0; j < 4; ++j) {
                cp_async16(dA[j] + s * STG_BYTES, sA[j] + (size_t)(kt + 2) * BK);
                cp_async16(dB[j] + s * STG_BYTES, sB[j] + (size_t)(kt + 2) * BK);
            }
        }
        asm volatile("cp.async.commit_group;" ::: "memory");

        const uint32_t so = sbase + (kt % 3) * STG_BYTES;
#pragma unroll
        for (int ks = 0; ks < 4; ++ks) {
            uint32_t a[2][4], b[8][2];
#pragma unroll
            for (int mt = 0; mt < 2; ++mt)
                asm volatile("ldmatrix.sync.aligned.m8n8.x4.shared.b16 {%0,%1,%2,%3}, [%4];"
                             : "=r"(a[mt][0]), "=r"(a[mt][1]), "=r"(a[mt][2]), "=r"(a[mt][3])
                             : "r"(so + offA[mt][ks]));
#pragma unroll
            for (int p = 0; p < 4; ++p)
                asm volatile("ldmatrix.sync.aligned.m8n8.x4.shared.b16 {%0,%1,%2,%3}, [%4];"
                             : "=r"(b[2 * p][0]), "=r"(b[2 * p][1]),
                               "=r"(b[2 * p + 1][0]), "=r"(b[2 * p + 1][1])
                             : "r"(so + offB[p][ks]));
#pragma unroll
            for (int mt = 0; mt < 2; ++mt)
#pragma unroll
                for (int nt = 0; nt < 8; ++nt)
                    asm volatile(
                        "mma.sync.aligned.m16n8k16.row.col.f32.f16.f16.f32 "
                        "{%0,%1,%2,%3}, {%4,%5,%6,%7}, {%8,%9}, {%0,%1,%2,%3};"
                        : "+f"(acc[mt][nt][0]), "+f"(acc[mt][nt][1]),
                          "+f"(acc[mt][nt][2]), "+f"(acc[mt][nt][3])
                        : "r"(a[mt][0]), "r"(a[mt][1]), "r"(a[mt][2]), "r"(a[mt][3]),
                          "r"(b[nt][0]), "r"(b[nt][1]));
        }
    }

    const int g = lane >> 2, cq = lane & 3;
#pragma unroll
    for (int mt = 0; mt < 2; ++mt) {
        int r0 = bm + warp_m * 32 + mt * 16 + g;
#pragma unroll
        for (int nt = 0; nt < 8; ++nt) {
            int col = bn + warp_n * 64 + nt * 8 + 2 * cq;
            float2 bb = *(const float2*)(bias + col);
            float2 v0 = make_float2(acc[mt][nt][0] + bb.x, acc[mt][nt][1] + bb.y);
            float2 v1 = make_float2(acc[mt][nt][2] + bb.x, acc[mt][nt][3] + bb.y);
            *(float2*)(C + (size_t)r0 * DIM + col) = v0;
            *(float2*)(C + (size_t)(r0 + 8) * DIM + col) = v1;
        }
    }
}

// ---------------------------------------------------------------------------
extern "C" void kernel_launch(void* const* d_in, const int* in_sizes, int n_in,
                              void* d_out, int out_size)
{
    const float* hidden      = (const float*)d_in[0];
    const float* slot_w      = (const float*)d_in[1];
    const float* slot_b      = (const float*)d_in[2];
    const float* leaf_logits = (const float*)d_in[3];
    const float* node_params = (const float*)d_in[4];
    const float* out_w       = (const float*)d_in[5];
    const float* out_b       = (const float*)d_in[6];
    float* out = (float*)d_out;

    cudaFuncSetAttribute(gemm_mma_kernel,
                         cudaFuncAttributeMaxDynamicSharedMemorySize, GEMM_SMEM);

    slots_kernel<<<T_TOK, 128>>>(hidden, slot_w, slot_b);
    softmax_kernel<<<(NW * NLEAF + 255) / 256, 256>>>(leaf_logits);
    transpose_kernel<<<dim3(NW / 32, DIM / 32), 256>>>(out_w);
    roots_mma_kernel<<<dim3(NW / 64, T_TOK / 32), 256>>>(node_params);
    gemm_mma_kernel<<<dim3(DIM / BN, T_TOK / BM), 256, GEMM_SMEM>>>(out_b, out);
}